// round 10
// baseline (speedup 1.0000x reference)
#include <cuda_runtime.h>
#include <cstdint>

// CausalDAG fused, warp-specialized persistent kernel for GB300 (sm_103a). R10.
//   m = A^T x (producer warps, exact fp32 fma2, emitted as bf16 hi/lo pairs)
//   h = elu(W1_c @ m + b1); out = W2_c @ h + b2   (bf16 m16n8k16, 3-mma comp)
//
// vs R9: producer reads A via float4 (4x fewer LDS instrs); x/out use streaming
// cache hints so prepacked weights stay L1-resident; phase-2/3 accumulator
// chains split (shorter mma dependency chains); phase-3 inside the tile loop
// (halves live H registers, funds the accumulator split).

#define Cc 16
#define Dd 64
#define Gg 32
#define NTH 512
#define ROWU2 36            // uint2 (hi,lo) pairs per row incl. pad -> conflict-free
#define CTU2 (16 * ROWU2)   // uint2 per (concept, tile) block = 576
#define TILEU2 (Cc * CTU2)  // 9216 uint2 = 73728 B per tile buffer

typedef unsigned long long ull;

// Prepacked bf16 hi/lo weight fragments.
// W1pk[((c*4+kt)*4+q)*32+lane], q: 0=hi(nt0,nt1) 1=hi(nt2,nt3) 2=lo(nt0,nt1) 3=lo(nt2,nt3)
// W2pk[((c*8+nt)*2+hl)*32+lane], uint4 = {b0(kt0),b1(kt0),b0(kt1),b1(kt1)}
__device__ uint4 W1pk[Cc * 4 * 4 * 32];
__device__ uint4 W2pk[Cc * 8 * 2 * 32];

__device__ __forceinline__ ull fma2(ull a, ull b, ull c) {
    ull d;
    asm("fma.rn.f32x2 %0, %1, %2, %3;" : "=l"(d) : "l"(a), "l"(b), "l"(c));
    return d;
}
__device__ __forceinline__ ull dup2(float a) {
    ull d;
    asm("mov.b64 %0, {%1, %1};" : "=l"(d) : "f"(a));
    return d;
}
__device__ __forceinline__ ull pk2(float a, float b) {
    ull d;
    asm("mov.b64 %0, {%1, %2};" : "=l"(d) : "f"(a), "f"(b));
    return d;
}
// pack two f32 -> bf16x2, first arg lands in lower 16 bits
__device__ __forceinline__ uint32_t pack_bf16_2(float lo, float hi) {
    uint32_t r;
    asm("cvt.rn.bf16x2.f32 %0, %1, %2;" : "=r"(r) : "f"(hi), "f"(lo));
    return r;
}
// fp32 pair -> bf16 hi pair + bf16 lo pair (residual)
__device__ __forceinline__ void split_pair(float f0, float f1,
                                           uint32_t& hi, uint32_t& lo) {
    hi = pack_bf16_2(f0, f1);
    float f0h = __uint_as_float(hi << 16);
    float f1h = __uint_as_float(hi & 0xffff0000u);
    lo = pack_bf16_2(f0 - f0h, f1 - f1h);
}
__device__ __forceinline__ void mma_bf16(float c[4],
                                         uint32_t a0, uint32_t a1, uint32_t a2, uint32_t a3,
                                         uint32_t b0, uint32_t b1) {
    asm volatile(
        "mma.sync.aligned.m16n8k16.row.col.f32.bf16.bf16.f32 "
        "{%0,%1,%2,%3}, {%4,%5,%6,%7}, {%8,%9}, {%0,%1,%2,%3};"
        : "+f"(c[0]), "+f"(c[1]), "+f"(c[2]), "+f"(c[3])
        : "r"(a0), "r"(a1), "r"(a2), "r"(a3), "r"(b0), "r"(b1));
}
__device__ __forceinline__ float elu1(float v) {
    return v > 0.0f ? v : (__expf(v) - 1.0f);
}

// ---------------- Prep: pack weights into bf16 hi/lo fragment order ----------
__global__ void __launch_bounds__(256)
pack_weights(const float* __restrict__ W1, const float* __restrict__ W2)
{
    const int t = blockIdx.x * 256 + threadIdx.x;   // 0..16383
    const int half = t >> 13;
    const int u = t & 8191;
    const int lane = u & 31;
    const int grp  = lane >> 2;
    const int tig  = lane & 3;

    uint4 v;
    if (half == 0) {
        const int q  = (u >> 5) & 3;
        const int kt = (u >> 7) & 3;
        const int c  = u >> 9;
        const bool lo_sel = q >= 2;
        const int ntA = (q & 1) * 2;
        #pragma unroll
        for (int j = 0; j < 2; j++) {
            const int nt = ntA + j;
            const int g  = nt * 8 + grp;
            const float* wr = W1 + ((size_t)c * Gg + g) * Dd + kt * 16 + 2 * tig;
            uint32_t h0, l0, h1, l1;
            split_pair(wr[0], wr[1], h0, l0);       // b0: k = 2tig, 2tig+1
            split_pair(wr[8], wr[9], h1, l1);       // b1: k = 2tig+8, 2tig+9
            if (j == 0) { v.x = lo_sel ? l0 : h0; v.y = lo_sel ? l1 : h1; }
            else        { v.z = lo_sel ? l0 : h0; v.w = lo_sel ? l1 : h1; }
        }
        W1pk[u] = v;
    } else {
        const int hl = (u >> 5) & 1;
        const int nt = (u >> 6) & 7;
        const int c  = u >> 9;
        const int d  = nt * 8 + grp;
        #pragma unroll
        for (int kt = 0; kt < 2; kt++) {
            const float* wr = W2 + ((size_t)c * Dd + d) * Gg + kt * 16 + 2 * tig;
            uint32_t h0, l0, h1, l1;
            split_pair(wr[0], wr[1], h0, l0);
            split_pair(wr[8], wr[9], h1, l1);
            uint32_t e0 = hl ? l0 : h0, e1 = hl ? l1 : h1;
            if (kt == 0) { v.x = e0; v.y = e1; }
            else         { v.z = e0; v.w = e1; }
        }
        W2pk[u] = v;
    }
}

extern __shared__ char smem_raw[];
// [0, 147456): two tile buffers of uint2 (hi,lo) bf16 pairs; [147456,+1K): A_s

__global__ void __launch_bounds__(NTH, 1)
causal_dag_kernel(const float* __restrict__ x,  const float* __restrict__ A,
                  const float* __restrict__ b1, const float* __restrict__ b2,
                  float* __restrict__ out, int nPairs)
{
    uint2* mbuf = (uint2*)smem_raw;
    float* A_s  = (float*)(smem_raw + 2 * TILEU2 * 8);
    const int tid = threadIdx.x;

    if (tid < 256) {
        // ======================= PRODUCER (warps 0-7) ========================
        A_s[tid] = A[tid];
        asm volatile("bar.sync 5, 256;" ::: "memory");

        const int bl = tid >> 4;               // 0..15 local batch row
        const int dq = tid & 15;               // float4 chunk of D=64
        int it = 0;
        for (int p = blockIdx.x; p < nPairs; p += gridDim.x, ++it) {
            #pragma unroll
            for (int sub = 0; sub < 2; sub++) {
                if (it > 0)
                    asm volatile("bar.sync %0, 512;" :: "r"(3 + sub) : "memory");
                const int tile = 2 * p + sub;
                const float4* xb =
                    (const float4*)(x + (size_t)(tile * 16 + bl) * (Cc * Dd)) + dq;

                ull mrx[Cc], mrz[Cc];
                #pragma unroll
                for (int i = 0; i < Cc; i++) { mrx[i] = 0ull; mrz[i] = 0ull; }
                #pragma unroll
                for (int j = 0; j < Cc; j++) {
                    float4 xv = __ldcs(xb + j * 16);        // streaming: evict-first
                    ull xlo = pk2(xv.x, xv.y);
                    ull xhi = pk2(xv.z, xv.w);
                    const float4* ar = (const float4*)(A_s + j * Cc);
                    #pragma unroll
                    for (int i4 = 0; i4 < 4; i4++) {
                        float4 av = ar[i4];                  // 1 LDS.128 = 4 A vals
                        float a4[4] = {av.x, av.y, av.z, av.w};
                        #pragma unroll
                        for (int ii = 0; ii < 4; ii++) {
                            ull a2 = dup2(a4[ii]);
                            mrx[i4 * 4 + ii] = fma2(a2, xlo, mrx[i4 * 4 + ii]);
                            mrz[i4 * 4 + ii] = fma2(a2, xhi, mrz[i4 * 4 + ii]);
                        }
                    }
                }
                uint2* buf = mbuf + sub * TILEU2;
                #pragma unroll
                for (int i = 0; i < Cc; i++) {
                    float f0, f1, g0, g1;
                    asm("mov.b64 {%0, %1}, %2;" : "=f"(f0), "=f"(f1) : "l"(mrx[i]));
                    asm("mov.b64 {%0, %1}, %2;" : "=f"(g0), "=f"(g1) : "l"(mrz[i]));
                    uint4 v;
                    split_pair(f0, f1, v.x, v.y);   // pair 2dq   : {hi, lo}
                    split_pair(g0, g1, v.z, v.w);   // pair 2dq+1 : {hi, lo}
                    *(uint4*)&buf[(i * 16 + bl) * ROWU2 + 2 * dq] = v;
                }
                asm volatile("bar.arrive %0, 512;" :: "r"(1 + sub) : "memory");
            }
        }
    } else {
        // ======================= CONSUMER (warps 8-15) =======================
        const int cw   = (tid >> 5) - 8;       // 0..7, owns concepts 2cw,2cw+1
        const int lane = tid & 31;
        const int grp  = lane >> 2;
        const int tig  = lane & 3;

        for (int p = blockIdx.x; p < nPairs; p += gridDim.x) {
            #pragma unroll
            for (int t = 0; t < 2; t++) {
                asm volatile("bar.sync %0, 512;" :: "r"(1 + t) : "memory");

                uint32_t hfh[2][8], hfl[2][8];  // H fragments for this tile
                #pragma unroll
                for (int s = 0; s < 2; s++) {
                    const int c = 2 * cw + s;
                    const uint2* mc = mbuf + t * TILEU2 + c * CTU2;

                    float acc[4][4], accC[4][4];   // hh-chain / compensation-chain
                    #pragma unroll
                    for (int nt = 0; nt < 4; nt++)
                        #pragma unroll
                        for (int q = 0; q < 4; q++) { acc[nt][q] = 0.0f; accC[nt][q] = 0.0f; }

                    #pragma unroll
                    for (int kt = 0; kt < 4; kt++) {
                        const int pi = kt * 8 + tig;
                        const uint2 a0 = mc[grp * ROWU2 + pi];
                        const uint2 a1 = mc[(grp + 8) * ROWU2 + pi];
                        const uint2 a2 = mc[grp * ROWU2 + pi + 4];
                        const uint2 a3 = mc[(grp + 8) * ROWU2 + pi + 4];
                        const int wb = ((c * 4 + kt) * 4) * 32 + lane;
                        const uint4 q0 = W1pk[wb];
                        const uint4 q1 = W1pk[wb + 32];
                        const uint4 q2 = W1pk[wb + 64];
                        const uint4 q3 = W1pk[wb + 96];
                        // hh terms -> acc (chain depth 4 over kt)
                        mma_bf16(acc[0], a0.x, a1.x, a2.x, a3.x, q0.x, q0.y);
                        mma_bf16(acc[1], a0.x, a1.x, a2.x, a3.x, q0.z, q0.w);
                        mma_bf16(acc[2], a0.x, a1.x, a2.x, a3.x, q1.x, q1.y);
                        mma_bf16(acc[3], a0.x, a1.x, a2.x, a3.x, q1.z, q1.w);
                        // lh + hl terms -> accC (chain depth 8 over kt)
                        mma_bf16(accC[0], a0.y, a1.y, a2.y, a3.y, q0.x, q0.y);
                        mma_bf16(accC[0], a0.x, a1.x, a2.x, a3.x, q2.x, q2.y);
                        mma_bf16(accC[1], a0.y, a1.y, a2.y, a3.y, q0.z, q0.w);
                        mma_bf16(accC[1], a0.x, a1.x, a2.x, a3.x, q2.z, q2.w);
                        mma_bf16(accC[2], a0.y, a1.y, a2.y, a3.y, q1.x, q1.y);
                        mma_bf16(accC[2], a0.x, a1.x, a2.x, a3.x, q3.x, q3.y);
                        mma_bf16(accC[3], a0.y, a1.y, a2.y, a3.y, q1.z, q1.w);
                        mma_bf16(accC[3], a0.x, a1.x, a2.x, a3.x, q3.z, q3.w);
                    }
                    // merge chains + bias + ELU + split to phase-3 A fragments
                    #pragma unroll
                    for (int nt = 0; nt < 4; nt++) {
                        const float2 bias = *(const float2*)&b1[c * Gg + nt * 8 + 2 * tig];
                        float v0 = elu1(acc[nt][0] + accC[nt][0] + bias.x);
                        float v1 = elu1(acc[nt][1] + accC[nt][1] + bias.y);
                        float v2 = elu1(acc[nt][2] + accC[nt][2] + bias.x);
                        float v3 = elu1(acc[nt][3] + accC[nt][3] + bias.y);
                        split_pair(v0, v1, hfh[s][2 * nt],     hfl[s][2 * nt]);
                        split_pair(v2, v3, hfh[s][2 * nt + 1], hfl[s][2 * nt + 1]);
                    }
                }
                asm volatile("bar.arrive %0, 512;" :: "r"(3 + t) : "memory");

                // ---------- Phase 3 for this tile (registers + weights only) --
                const int b0 = (2 * p + t) * 16;
                #pragma unroll
                for (int s = 0; s < 2; s++) {
                    const int c = 2 * cw + s;
                    const uint32_t* hh = hfh[s];
                    const uint32_t* hl = hfl[s];
                    #pragma unroll
                    for (int nt = 0; nt < 8; nt++) {
                        const int wb = ((c * 8 + nt) * 2) * 32 + lane;
                        const uint4 gh = W2pk[wb];
                        const uint4 gl = W2pk[wb + 32];
                        const float2 bias = *(const float2*)&b2[c * Dd + nt * 8 + 2 * tig];
                        float o[4]  = {0.0f, 0.0f, 0.0f, 0.0f};
                        float oC[4] = {0.0f, 0.0f, 0.0f, 0.0f};
                        // kt'=0
                        mma_bf16(o,  hh[0], hh[1], hh[2], hh[3], gh.x, gh.y);
                        mma_bf16(o,  hh[0], hh[1], hh[2], hh[3], gl.x, gl.y);
                        mma_bf16(oC, hl[0], hl[1], hl[2], hl[3], gh.x, gh.y);
                        // kt'=1
                        mma_bf16(o,  hh[4], hh[5], hh[6], hh[7], gh.z, gh.w);
                        mma_bf16(o,  hh[4], hh[5], hh[6], hh[7], gl.z, gl.w);
                        mma_bf16(oC, hl[4], hl[5], hl[6], hl[7], gh.z, gh.w);

                        float2 v0; v0.x = o[0] + oC[0] + bias.x; v0.y = o[1] + oC[1] + bias.y;
                        float2 v1; v1.x = o[2] + oC[2] + bias.x; v1.y = o[3] + oC[3] + bias.y;
                        __stcs((float2*)(out + ((size_t)(b0 + grp) * Cc + c) * Dd
                                             + nt * 8 + 2 * tig), v0);
                        __stcs((float2*)(out + ((size_t)(b0 + grp + 8) * Cc + c) * Dd
                                             + nt * 8 + 2 * tig), v1);
                    }
                }
            }
        }
    }
}

extern "C" void kernel_launch(void* const* d_in, const int* in_sizes, int n_in,
                              void* d_out, int out_size)
{
    const float* x  = (const float*)d_in[0];
    const float* A  = (const float*)d_in[1];
    const float* W1 = (const float*)d_in[2];
    const float* b1 = (const float*)d_in[3];
    const float* W2 = (const float*)d_in[4];
    const float* b2 = (const float*)d_in[5];
    float* out = (float*)d_out;

    const int Btot   = in_sizes[0] / (Cc * Dd);        // 65536
    const int nPairs = Btot / 32;                      // 2048

    int sms = 148;
    cudaDeviceGetAttribute(&sms, cudaDevAttrMultiProcessorCount, 0);

    const int smem_bytes = 2 * TILEU2 * 8 + 1024;      // 148480 B

    pack_weights<<<64, 256>>>(W1, W2);

    cudaFuncSetAttribute(causal_dag_kernel,
                         cudaFuncAttributeMaxDynamicSharedMemorySize, smem_bytes);
    causal_dag_kernel<<<sms, NTH, smem_bytes>>>(x, A, b1, b2, out, nPairs);
}

// round 11
// speedup vs baseline: 1.2649x; 1.2649x over previous
#include <cuda_runtime.h>
#include <cstdint>

// CausalDAG fused, warp-specialized persistent kernel for GB300 (sm_103a). R11.
//   m = A^T x (producer warps, exact fp32 fma2, emitted as bf16 hi/lo pairs)
//   h = elu(W1_c @ m + b1); out = W2_c @ h + b2   (bf16 m16n8k16, 3-mma comp)
//
// Base = R8 (best: 177us). Changes:
//  * W1-hi weight fragments staged in smem once per CTA (64 KB): the
//    un-amortized weight stream becomes LDS instead of 234-cyc L2 LDG.
//  * Producer reads A rows via float4 (4x fewer LDS in the mix loop).

#define Cc 16
#define Dd 64
#define Gg 32
#define NTH 512
#define ROWU2 36            // uint2 (hi,lo) pairs per row incl. pad
#define CTU2 (16 * ROWU2)   // uint2 per (concept, tile) block = 576
#define TILEU2 (Cc * CTU2)  // 9216 uint2 = 73728 B per tile buffer

typedef unsigned long long ull;

// Prepacked bf16 hi/lo weight fragments.
// W1pk[((c*4+kt)*4+q)*32+lane], q: 0=hi(nt0,nt1) 1=hi(nt2,nt3) 2=lo(nt0,nt1) 3=lo(nt2,nt3)
// W2pk[((c*8+nt)*2+hl)*32+lane], uint4 = {b0(kt0),b1(kt0),b0(kt1),b1(kt1)}
__device__ uint4 W1pk[Cc * 4 * 4 * 32];
__device__ uint4 W2pk[Cc * 8 * 2 * 32];

__device__ __forceinline__ ull fma2(ull a, ull b, ull c) {
    ull d;
    asm("fma.rn.f32x2 %0, %1, %2, %3;" : "=l"(d) : "l"(a), "l"(b), "l"(c));
    return d;
}
__device__ __forceinline__ ull dup2(float a) {
    ull d;
    asm("mov.b64 %0, {%1, %1};" : "=l"(d) : "f"(a));
    return d;
}
// pack two f32 -> bf16x2, first arg lands in lower 16 bits
__device__ __forceinline__ uint32_t pack_bf16_2(float lo, float hi) {
    uint32_t r;
    asm("cvt.rn.bf16x2.f32 %0, %1, %2;" : "=r"(r) : "f"(hi), "f"(lo));
    return r;
}
// fp32 pair -> bf16 hi pair + bf16 lo pair (residual)
__device__ __forceinline__ void split_pair(float f0, float f1,
                                           uint32_t& hi, uint32_t& lo) {
    hi = pack_bf16_2(f0, f1);
    float f0h = __uint_as_float(hi << 16);
    float f1h = __uint_as_float(hi & 0xffff0000u);
    lo = pack_bf16_2(f0 - f0h, f1 - f1h);
}
__device__ __forceinline__ void mma_bf16(float c[4],
                                         uint32_t a0, uint32_t a1, uint32_t a2, uint32_t a3,
                                         uint32_t b0, uint32_t b1) {
    asm volatile(
        "mma.sync.aligned.m16n8k16.row.col.f32.bf16.bf16.f32 "
        "{%0,%1,%2,%3}, {%4,%5,%6,%7}, {%8,%9}, {%0,%1,%2,%3};"
        : "+f"(c[0]), "+f"(c[1]), "+f"(c[2]), "+f"(c[3])
        : "r"(a0), "r"(a1), "r"(a2), "r"(a3), "r"(b0), "r"(b1));
}
__device__ __forceinline__ float elu1(float v) {
    return v > 0.0f ? v : (__expf(v) - 1.0f);
}

// ---------------- Prep: pack weights into bf16 hi/lo fragment order ----------
__global__ void __launch_bounds__(256)
pack_weights(const float* __restrict__ W1, const float* __restrict__ W2)
{
    const int t = blockIdx.x * 256 + threadIdx.x;   // 0..16383
    const int half = t >> 13;
    const int u = t & 8191;
    const int lane = u & 31;
    const int grp  = lane >> 2;
    const int tig  = lane & 3;

    uint4 v;
    if (half == 0) {
        const int q  = (u >> 5) & 3;
        const int kt = (u >> 7) & 3;
        const int c  = u >> 9;
        const bool lo_sel = q >= 2;
        const int ntA = (q & 1) * 2;
        #pragma unroll
        for (int j = 0; j < 2; j++) {
            const int nt = ntA + j;
            const int g  = nt * 8 + grp;
            const float* wr = W1 + ((size_t)c * Gg + g) * Dd + kt * 16 + 2 * tig;
            uint32_t h0, l0, h1, l1;
            split_pair(wr[0], wr[1], h0, l0);       // b0: k = 2tig, 2tig+1
            split_pair(wr[8], wr[9], h1, l1);       // b1: k = 2tig+8, 2tig+9
            if (j == 0) { v.x = lo_sel ? l0 : h0; v.y = lo_sel ? l1 : h1; }
            else        { v.z = lo_sel ? l0 : h0; v.w = lo_sel ? l1 : h1; }
        }
        W1pk[u] = v;
    } else {
        const int hl = (u >> 5) & 1;
        const int nt = (u >> 6) & 7;
        const int c  = u >> 9;
        const int d  = nt * 8 + grp;
        #pragma unroll
        for (int kt = 0; kt < 2; kt++) {
            const float* wr = W2 + ((size_t)c * Dd + d) * Gg + kt * 16 + 2 * tig;
            uint32_t h0, l0, h1, l1;
            split_pair(wr[0], wr[1], h0, l0);
            split_pair(wr[8], wr[9], h1, l1);
            uint32_t e0 = hl ? l0 : h0, e1 = hl ? l1 : h1;
            if (kt == 0) { v.x = e0; v.y = e1; }
            else         { v.z = e0; v.w = e1; }
        }
        W2pk[u] = v;
    }
}

extern __shared__ char smem_raw[];
// [0, 147456): two m tile buffers (uint2 (hi,lo) bf16 pairs)
// [147456, 212992): W1-hi fragment cache (4096 uint4 = 64 KB)
// [212992, 214016): A_s (256 floats) + pad

__global__ void __launch_bounds__(NTH, 1)
causal_dag_kernel(const float* __restrict__ x,  const float* __restrict__ A,
                  const float* __restrict__ b1, const float* __restrict__ b2,
                  float* __restrict__ out, int nPairs)
{
    uint2* mbuf  = (uint2*)smem_raw;
    uint4* W1h_s = (uint4*)(smem_raw + 2 * TILEU2 * 8);
    float* A_s   = (float*)(smem_raw + 2 * TILEU2 * 8 + 65536);
    const int tid = threadIdx.x;

    // ---- common preamble: stage A and W1-hi fragments into smem -------------
    if (tid < 256) A_s[tid] = A[tid];
    // W1h_s[(ck*2+q)*32+lane] = W1pk[(ck*4+q)*32+lane], q in {0,1} (hi halves)
    #pragma unroll
    for (int r = 0; r < 8; r++) {
        const int idx  = r * NTH + tid;            // 0..4095
        const int lane = idx & 31;
        const int q    = (idx >> 5) & 1;
        const int ck   = idx >> 6;                 // (c*4+kt) 0..63
        W1h_s[idx] = W1pk[(ck * 4 + q) * 32 + lane];
    }
    __syncthreads();

    if (tid < 256) {
        // ======================= PRODUCER (warps 0-7) ========================
        const int bl = tid >> 4;               // 0..15 local batch row
        const int dq = tid & 15;               // float4 chunk of D=64
        int it = 0;
        for (int p = blockIdx.x; p < nPairs; p += gridDim.x, ++it) {
            #pragma unroll
            for (int sub = 0; sub < 2; sub++) {
                if (it > 0)
                    asm volatile("bar.sync %0, 512;" :: "r"(3 + sub) : "memory");
                const int tile = 2 * p + sub;
                const ulonglong2* xb =
                    (const ulonglong2*)(x + (size_t)(tile * 16 + bl) * (Cc * Dd)) + dq;

                ull mrx[Cc], mrz[Cc];
                #pragma unroll
                for (int i = 0; i < Cc; i++) { mrx[i] = 0ull; mrz[i] = 0ull; }
                #pragma unroll
                for (int j = 0; j < Cc; j++) {
                    ulonglong2 xv = xb[j * 16];
                    const float4* ar = (const float4*)(A_s + j * Cc);
                    #pragma unroll
                    for (int i4 = 0; i4 < 4; i4++) {
                        float4 av = ar[i4];              // 1 LDS.128 = 4 A values
                        float a4[4] = {av.x, av.y, av.z, av.w};
                        #pragma unroll
                        for (int ii = 0; ii < 4; ii++) {
                            ull a2 = dup2(a4[ii]);
                            mrx[i4 * 4 + ii] = fma2(a2, xv.x, mrx[i4 * 4 + ii]);
                            mrz[i4 * 4 + ii] = fma2(a2, xv.y, mrz[i4 * 4 + ii]);
                        }
                    }
                }
                uint2* buf = mbuf + sub * TILEU2;
                #pragma unroll
                for (int i = 0; i < Cc; i++) {
                    float f0, f1, g0, g1;
                    asm("mov.b64 {%0, %1}, %2;" : "=f"(f0), "=f"(f1) : "l"(mrx[i]));
                    asm("mov.b64 {%0, %1}, %2;" : "=f"(g0), "=f"(g1) : "l"(mrz[i]));
                    uint4 v;
                    split_pair(f0, f1, v.x, v.y);   // pair 2dq   : {hi, lo}
                    split_pair(g0, g1, v.z, v.w);   // pair 2dq+1 : {hi, lo}
                    *(uint4*)&buf[(i * 16 + bl) * ROWU2 + 2 * dq] = v;
                }
                asm volatile("bar.arrive %0, 512;" :: "r"(1 + sub) : "memory");
            }
        }
    } else {
        // ======================= CONSUMER (warps 8-15) =======================
        const int cw   = (tid >> 5) - 8;       // 0..7, owns concepts 2cw,2cw+1
        const int lane = tid & 31;
        const int grp  = lane >> 2;
        const int tig  = lane & 3;

        for (int p = blockIdx.x; p < nPairs; p += gridDim.x) {
            uint32_t hfh[2][2][8], hfl[2][2][8];   // [s][t][kt'*4+r] bf16 pairs

            #pragma unroll
            for (int t = 0; t < 2; t++) {
                asm volatile("bar.sync %0, 512;" :: "r"(1 + t) : "memory");
                #pragma unroll
                for (int s = 0; s < 2; s++) {
                    const int c = 2 * cw + s;
                    const uint2* mc = mbuf + t * TILEU2 + c * CTU2;

                    float acc[4][4];
                    #pragma unroll
                    for (int nt = 0; nt < 4; nt++)
                        #pragma unroll
                        for (int q = 0; q < 4; q++) acc[nt][q] = 0.0f;

                    #pragma unroll
                    for (int kt = 0; kt < 4; kt++) {
                        const int pi = kt * 8 + tig;
                        const uint2 a0 = mc[grp * ROWU2 + pi];
                        const uint2 a1 = mc[(grp + 8) * ROWU2 + pi];
                        const uint2 a2 = mc[grp * ROWU2 + pi + 4];
                        const uint2 a3 = mc[(grp + 8) * ROWU2 + pi + 4];
                        // hi fragments from smem cache, lo from L2
                        const int wh = ((c * 4 + kt) * 2) * 32 + lane;
                        const uint4 q0 = W1h_s[wh];
                        const uint4 q1 = W1h_s[wh + 32];
                        const int wl = ((c * 4 + kt) * 4 + 2) * 32 + lane;
                        const uint4 q2 = W1pk[wl];
                        const uint4 q3 = W1pk[wl + 32];
                        // nt0
                        mma_bf16(acc[0], a0.x, a1.x, a2.x, a3.x, q0.x, q0.y);
                        mma_bf16(acc[0], a0.y, a1.y, a2.y, a3.y, q0.x, q0.y);
                        mma_bf16(acc[0], a0.x, a1.x, a2.x, a3.x, q2.x, q2.y);
                        // nt1
                        mma_bf16(acc[1], a0.x, a1.x, a2.x, a3.x, q0.z, q0.w);
                        mma_bf16(acc[1], a0.y, a1.y, a2.y, a3.y, q0.z, q0.w);
                        mma_bf16(acc[1], a0.x, a1.x, a2.x, a3.x, q2.z, q2.w);
                        // nt2
                        mma_bf16(acc[2], a0.x, a1.x, a2.x, a3.x, q1.x, q1.y);
                        mma_bf16(acc[2], a0.y, a1.y, a2.y, a3.y, q1.x, q1.y);
                        mma_bf16(acc[2], a0.x, a1.x, a2.x, a3.x, q3.x, q3.y);
                        // nt3
                        mma_bf16(acc[3], a0.x, a1.x, a2.x, a3.x, q1.z, q1.w);
                        mma_bf16(acc[3], a0.y, a1.y, a2.y, a3.y, q1.z, q1.w);
                        mma_bf16(acc[3], a0.x, a1.x, a2.x, a3.x, q3.z, q3.w);
                    }
                    // bias + ELU + split to bf16 hi/lo (phase-3 A fragments)
                    #pragma unroll
                    for (int nt = 0; nt < 4; nt++) {
                        const float2 bias = *(const float2*)&b1[c * Gg + nt * 8 + 2 * tig];
                        float v0 = elu1(acc[nt][0] + bias.x);
                        float v1 = elu1(acc[nt][1] + bias.y);
                        float v2 = elu1(acc[nt][2] + bias.x);
                        float v3 = elu1(acc[nt][3] + bias.y);
                        split_pair(v0, v1, hfh[s][t][2 * nt],     hfl[s][t][2 * nt]);
                        split_pair(v2, v3, hfh[s][t][2 * nt + 1], hfl[s][t][2 * nt + 1]);
                    }
                }
                asm volatile("bar.arrive %0, 512;" :: "r"(3 + t) : "memory");
            }

            // ---------- Phase 3: Out = H @ W2^T + b2 (registers only) --------
            #pragma unroll
            for (int s = 0; s < 2; s++) {
                const int c = 2 * cw + s;
                #pragma unroll
                for (int nt = 0; nt < 8; nt++) {
                    const int wb = ((c * 8 + nt) * 2) * 32 + lane;
                    const uint4 gh = W2pk[wb];
                    const uint4 gl = W2pk[wb + 32];
                    const float2 bias = *(const float2*)&b2[c * Dd + nt * 8 + 2 * tig];
                    #pragma unroll
                    for (int t = 0; t < 2; t++) {
                        const uint32_t* hh = hfh[s][t];
                        const uint32_t* hl = hfl[s][t];
                        float o[4] = {0.0f, 0.0f, 0.0f, 0.0f};
                        // kt'=0
                        mma_bf16(o, hh[0], hh[1], hh[2], hh[3], gh.x, gh.y);
                        mma_bf16(o, hl[0], hl[1], hl[2], hl[3], gh.x, gh.y);
                        mma_bf16(o, hh[0], hh[1], hh[2], hh[3], gl.x, gl.y);
                        // kt'=1
                        mma_bf16(o, hh[4], hh[5], hh[6], hh[7], gh.z, gh.w);
                        mma_bf16(o, hl[4], hl[5], hl[6], hl[7], gh.z, gh.w);
                        mma_bf16(o, hh[4], hh[5], hh[6], hh[7], gl.z, gl.w);

                        const int b0 = (2 * p + t) * 16;
                        float2 v0; v0.x = o[0] + bias.x; v0.y = o[1] + bias.y;
                        float2 v1; v1.x = o[2] + bias.x; v1.y = o[3] + bias.y;
                        *(float2*)(out + ((size_t)(b0 + grp) * Cc + c) * Dd
                                       + nt * 8 + 2 * tig) = v0;
                        *(float2*)(out + ((size_t)(b0 + grp + 8) * Cc + c) * Dd
                                       + nt * 8 + 2 * tig) = v1;
                    }
                }
            }
        }
    }
}

extern "C" void kernel_launch(void* const* d_in, const int* in_sizes, int n_in,
                              void* d_out, int out_size)
{
    const float* x  = (const float*)d_in[0];
    const float* A  = (const float*)d_in[1];
    const float* W1 = (const float*)d_in[2];
    const float* b1 = (const float*)d_in[3];
    const float* W2 = (const float*)d_in[4];
    const float* b2 = (const float*)d_in[5];
    float* out = (float*)d_out;

    const int Btot   = in_sizes[0] / (Cc * Dd);        // 65536
    const int nPairs = Btot / 32;                      // 2048

    int sms = 148;
    cudaDeviceGetAttribute(&sms, cudaDevAttrMultiProcessorCount, 0);

    const int smem_bytes = 2 * TILEU2 * 8 + 65536 + 1024;   // 214016 B

    pack_weights<<<64, 256>>>(W1, W2);

    cudaFuncSetAttribute(causal_dag_kernel,
                         cudaFuncAttributeMaxDynamicSharedMemorySize, smem_bytes);
    causal_dag_kernel<<<sms, NTH, smem_bytes>>>(x, A, b1, b2, out, nPairs);
}